// round 6
// baseline (speedup 1.0000x reference)
#include <cuda_runtime.h>
#include <cuda_bf16.h>
#include <stdint.h>

#define GRID 64
#define NVOX (GRID*GRID*GRID)          // 262144
#define SCAN_BLOCK 1024
#define SCAN_NBLOCKS (NVOX / SCAN_BLOCK)  // 256

// -------- device scratch (no allocation allowed) --------
__device__ float        g_sums[NVOX * 8];     // 7 feature sums + count (8 MB)
__device__ int          g_rank[NVOX];         // local exclusive prefix within scan block
__device__ int          g_blockSums[SCAN_NBLOCKS];
__device__ int          g_blockOff[SCAN_NBLOCKS];
__device__ int          g_unq[NVOX];          // sorted unique lin ids
__device__ int          g_nuniq;
__device__ unsigned int g_sawOddNonzero;      // dtype detection flag

// -------- helpers --------
__device__ __forceinline__ void red_add_v4(float* addr, float a, float b, float c, float d) {
    asm volatile("red.global.add.v4.f32 [%0], {%1, %2, %3, %4};"
                 :: "l"(addr), "f"(a), "f"(b), "f"(c), "f"(d) : "memory");
}

// -------- kernels --------
__global__ void k_zero() {
    // zero g_sums as float4 (NVOX*8 floats = 524288 float4)
    int i = blockIdx.x * blockDim.x + threadIdx.x;
    float4* s4 = reinterpret_cast<float4*>(g_sums);
    const int n4 = NVOX * 8 / 4;
    if (i < n4) s4[i] = make_float4(0.f, 0.f, 0.f, 0.f);
    if (i == 0) g_sawOddNonzero = 0u;
}

// Detect whether grid_ind is int64 (odd 32-bit words are high words == 0)
// or int32 (odd words are real coords, nonzero w.p. 63/64 each).
__global__ void k_detect(const unsigned int* __restrict__ g, long long nwords) {
    int t = threadIdx.x;  // 256 threads, 1 block
    long long idx = (long long)t * 24694LL + 1LL;  // odd, spread over first ~6.3M words
    if (idx < nwords) {
        if (g[idx] != 0u) atomicOr(&g_sawOddNonzero, 1u);
    }
}

__global__ void __launch_bounds__(256)
k_accumulate(const float* __restrict__ pts, const void* __restrict__ grid, int N) {
    int i = blockIdx.x * blockDim.x + threadIdx.x;
    if (i >= N) return;
    const bool is64 = (g_sawOddNonzero == 0u);
    int g0, g1, g2;
    if (is64) {
        const long long* g = (const long long*)grid;
        g0 = (int)g[3LL * i]; g1 = (int)g[3LL * i + 1]; g2 = (int)g[3LL * i + 2];
    } else {
        const int* g = (const int*)grid;
        g0 = g[3 * i]; g1 = g[3 * i + 1]; g2 = g[3 * i + 2];
    }
    int lin = (g0 * GRID + g1) * GRID + g2;
    const float* p = pts + (size_t)7 * i;
    float p0 = p[0], p1 = p[1], p2 = p[2], p3 = p[3], p4 = p[4], p5 = p[5], p6 = p[6];
    float* s = &g_sums[(size_t)lin * 8];
    red_add_v4(s,     p0, p1, p2, p3);
    red_add_v4(s + 4, p4, p5, p6, 1.0f);
}

__global__ void __launch_bounds__(SCAN_BLOCK)
k_scanA() {
    __shared__ int s[SCAN_BLOCK];
    int t = threadIdx.x;
    int idx = blockIdx.x * SCAN_BLOCK + t;
    int occ = (g_sums[(size_t)idx * 8 + 7] > 0.0f) ? 1 : 0;
    s[t] = occ;
    __syncthreads();
    #pragma unroll
    for (int off = 1; off < SCAN_BLOCK; off <<= 1) {
        int x = (t >= off) ? s[t - off] : 0;
        __syncthreads();
        s[t] += x;
        __syncthreads();
    }
    g_rank[idx] = s[t] - occ;           // local exclusive prefix
    if (t == SCAN_BLOCK - 1) g_blockSums[blockIdx.x] = s[t];
}

__global__ void __launch_bounds__(SCAN_NBLOCKS)
k_scanB() {
    __shared__ int s[SCAN_NBLOCKS];
    int t = threadIdx.x;
    int v = g_blockSums[t];
    s[t] = v;
    __syncthreads();
    #pragma unroll
    for (int off = 1; off < SCAN_NBLOCKS; off <<= 1) {
        int x = (t >= off) ? s[t - off] : 0;
        __syncthreads();
        s[t] += x;
        __syncthreads();
    }
    g_blockOff[t] = s[t] - v;           // exclusive
    if (t == SCAN_NBLOCKS - 1) g_nuniq = s[t];
}

__global__ void __launch_bounds__(SCAN_BLOCK)
k_scatter() {
    int t = threadIdx.x;
    int idx = blockIdx.x * SCAN_BLOCK + t;
    if (g_sums[(size_t)idx * 8 + 7] > 0.0f) {
        int r = g_blockOff[blockIdx.x] + g_rank[idx];
        g_unq[r] = idx;
    }
}

// Write the head (valid unique rows): mean and decoded coords.
__global__ void __launch_bounds__(256)
k_head(float* __restrict__ out, int N) {
    int r = blockIdx.x * blockDim.x + threadIdx.x;
    int nu = g_nuniq;
    if (r >= nu) return;
    int lin = g_unq[r];
    const float* s = &g_sums[(size_t)lin * 8];
    float cnt = s[7];
    float inv = 1.0f / fmaxf(cnt, 1.0f);
    float* om = out + (size_t)7 * r;
    #pragma unroll
    for (int f = 0; f < 7; f++) om[f] = s[f] * inv;
    float* ou = out + (size_t)7 * N + (size_t)3 * r;
    ou[0] = (float)(lin >> 12);
    ou[1] = (float)((lin >> 6) & 63);
    ou[2] = (float)(lin & 63);
}

// Fill padded tail: zeros in the mean region, -1 in the unq3 region.
__global__ void __launch_bounds__(256)
k_tail(float* __restrict__ out, int N) {
    long long total = 10LL * N;
    long long n7 = 7LL * N;
    int nu = g_nuniq;
    long long b1 = 7LL * nu;        // mean-region head/tail boundary
    long long b2 = n7 + 3LL * nu;   // unq-region head/tail boundary
    long long i4 = (long long)blockIdx.x * blockDim.x + threadIdx.x;
    long long e = 4LL * i4;
    if (e >= total) return;
    if (e + 4 <= n7) {
        if (e >= b1) {
            *reinterpret_cast<float4*>(out + e) = make_float4(0.f, 0.f, 0.f, 0.f);
        } else if (e + 4 > b1) {
            #pragma unroll
            for (int j = 0; j < 4; j++)
                if (e + j >= b1) out[e + j] = 0.f;
        }
    } else if (e >= n7 && e + 4 <= total) {
        if (e >= b2) {
            *reinterpret_cast<float4*>(out + e) = make_float4(-1.f, -1.f, -1.f, -1.f);
        } else if (e + 4 > b2) {
            #pragma unroll
            for (int j = 0; j < 4; j++)
                if (e + j >= b2) out[e + j] = -1.f;
        }
    } else {
        // straddles the mean/unq boundary or the end of the buffer
        #pragma unroll
        for (int j = 0; j < 4; j++) {
            long long idx = e + j;
            if (idx >= total) break;
            if (idx < n7) {
                if (idx >= b1) out[idx] = 0.f;
            } else {
                if (idx >= b2) out[idx] = -1.f;
            }
        }
    }
}

extern "C" void kernel_launch(void* const* d_in, const int* in_sizes, int n_in,
                              void* d_out, int out_size) {
    const float* pts = (const float*)d_in[0];
    const void* grid = d_in[1];
    const int N = in_sizes[0] / 7;
    float* out = (float*)d_out;

    // 1. zero scratch
    {
        int n4 = NVOX * 8 / 4;
        k_zero<<<(n4 + 255) / 256, 256>>>();
    }
    // 2. detect grid_ind dtype (int32 vs int64)
    k_detect<<<1, 256>>>((const unsigned int*)grid, 3LL * N);
    // 3. accumulate sums + counts via vector reductions
    k_accumulate<<<(N + 255) / 256, 256>>>(pts, grid, N);
    // 4. sorted-unique ranks via scan
    k_scanA<<<SCAN_NBLOCKS, SCAN_BLOCK>>>();
    k_scanB<<<1, SCAN_NBLOCKS>>>();
    k_scatter<<<SCAN_NBLOCKS, SCAN_BLOCK>>>();
    // 5. head rows (valid voxels)
    k_head<<<(NVOX + 255) / 256, 256>>>(out, N);
    // 6. padded tail fill (bulk of the output bytes)
    {
        long long total = 10LL * N;
        long long n4 = (total + 3) / 4;
        int blocks = (int)((n4 + 255) / 256);
        k_tail<<<blocks, 256>>>(out, N);
    }
}

// round 9
// speedup vs baseline: 1.0951x; 1.0951x over previous
#include <cuda_runtime.h>
#include <cuda_bf16.h>
#include <stdint.h>

#define GRIDG 64
#define NVOX (GRIDG*GRIDG*GRIDG)            // 262144
#define SCAN_BLOCK 1024
#define SCAN_NBLOCKS (NVOX / SCAN_BLOCK)    // 256

// -------- device scratch (no allocation allowed) --------
__device__ float        g_sums[NVOX * 8];           // 7 feature sums + count (8 MB)
__device__ int          g_blockSums[SCAN_NBLOCKS];
__device__ int          g_nuniq;
__device__ unsigned int g_sawOddNonzero = 0u;       // monotone: OR-only, idempotent

// -------- helpers --------
__device__ __forceinline__ void red_add_v4(float* addr, float a, float b, float c, float d) {
    asm volatile("red.global.add.v4.f32 [%0], {%1, %2, %3, %4};"
                 :: "l"(addr), "f"(a), "f"(b), "f"(c), "f"(d) : "memory");
}

// fill elements [lo, hi) of out with val; grid-stride over (tid, nth) lanes
__device__ __forceinline__ void fill_span(float* out, long long lo, long long hi,
                                          float val, long long tid, long long nth) {
    if (lo >= hi) return;
    long long alo = (lo + 3) & ~3LL; if (alo > hi) alo = hi;
    long long ahi = hi & ~3LL;       if (ahi < alo) ahi = alo;
    if (tid < (alo - lo)) out[lo + tid] = val;      // unaligned head (<4)
    if (tid < (hi - ahi)) out[ahi + tid] = val;     // unaligned tail (<4)
    long long n4 = (ahi - alo) >> 2;
    float4  v4 = make_float4(val, val, val, val);
    float4* p  = reinterpret_cast<float4*>(out + alo);
    for (long long k = tid; k < n4; k += nth) p[k] = v4;
}

// -------- K1: zero sums (+ dtype detect in the extra block) --------
// grid = ZBLK + 1; last block samples odd 32-bit words of grid_ind:
// all-zero => int64 (high words), any nonzero => int32.
#define ZBLK ((NVOX * 8 / 4 + 255) / 256)   // 2048
__global__ void __launch_bounds__(256)
k_init(const unsigned int* __restrict__ g, long long nwords) {
    if (blockIdx.x == ZBLK) {
        long long idx = (long long)threadIdx.x * 24694LL + 1LL; // odd words
        if (idx < nwords && g[idx] != 0u) atomicOr(&g_sawOddNonzero, 1u);
        return;
    }
    int i = blockIdx.x * 256 + threadIdx.x;
    reinterpret_cast<float4*>(g_sums)[i] = make_float4(0.f, 0.f, 0.f, 0.f);
}

// -------- K2: fused accumulate (SMEM-staged) + guaranteed-tail fill --------
__global__ void __launch_bounds__(256)
k_acc_fill(const float* __restrict__ pts, const void* __restrict__ grid,
           int N, int A, int F, float* __restrict__ out, long long NM) {
    const int bid = blockIdx.x;
    const long long T = (long long)A + F;
    const long long before = (long long)bid * F / T;         // fills before bid
    const bool is_fill = ((long long)(bid + 1) * F / T) > before;

    if (is_fill) {
        // guaranteed tail: [7*NM, 7N) = 0,  [7N+3*NM, 10N) = -1
        long long tid = before * 256 + threadIdx.x;
        long long nth = (long long)F * 256;
        long long n7  = 7LL * N;
        fill_span(out, 7LL * NM,      n7,       0.f, tid, nth);
        fill_span(out, n7 + 3LL * NM, 10LL * N, -1.f, tid, nth);
        return;
    }

    __shared__ float sp[256 * 7];   // 7168 B
    __shared__ int   si[256 * 6];   // 6144 B (int64 worst case)
    const int t      = threadIdx.x;
    const int acc_id = bid - (int)before;
    const int p0     = acc_id * 256;
    const int npts   = min(256, N - p0);
    const bool is64  = (g_sawOddNonzero == 0u);

    // stage points (coalesced float4 for full blocks)
    {
        const float* src = pts + (long long)p0 * 7;
        if (npts == 256) {
            const float4* s4 = reinterpret_cast<const float4*>(src);
            float4*       d4 = reinterpret_cast<float4*>(sp);
            #pragma unroll 2
            for (int k = t; k < 448; k += 256) d4[k] = s4[k];
        } else {
            for (int k = t; k < npts * 7; k += 256) sp[k] = src[k];
        }
    }
    // stage indices (coalesced int4 for full blocks)
    if (is64) {
        const int* src = (const int*)grid + (long long)p0 * 6;
        if (npts == 256) {
            const int4* s4 = reinterpret_cast<const int4*>(src);
            int4*       d4 = reinterpret_cast<int4*>(si);
            #pragma unroll 2
            for (int k = t; k < 384; k += 256) d4[k] = s4[k];
        } else {
            for (int k = t; k < npts * 6; k += 256) si[k] = src[k];
        }
    } else {
        const int* src = (const int*)grid + (long long)p0 * 3;
        if (npts == 256) {
            const int4* s4 = reinterpret_cast<const int4*>(src);
            int4*       d4 = reinterpret_cast<int4*>(si);
            for (int k = t; k < 192; k += 256) d4[k] = s4[k];
        } else {
            for (int k = t; k < npts * 3; k += 256) si[k] = src[k];
        }
    }
    __syncthreads();

    if (t < npts) {
        int g0, g1, g2;
        if (is64) { g0 = si[6*t]; g1 = si[6*t + 2]; g2 = si[6*t + 4]; }
        else      { g0 = si[3*t]; g1 = si[3*t + 1]; g2 = si[3*t + 2]; }
        int lin = (g0 * GRIDG + g1) * GRIDG + g2;
        const float* q = &sp[7 * t];
        float* s = &g_sums[(long long)lin * 8];
        red_add_v4(s,     q[0], q[1], q[2], q[3]);
        red_add_v4(s + 4, q[4], q[5], q[6], 1.0f);
    }
}

// -------- K3a: per-scan-block occupancy sums (ballot) --------
__global__ void __launch_bounds__(SCAN_BLOCK)
k_scanA() {
    int t = threadIdx.x;
    int idx = blockIdx.x * SCAN_BLOCK + t;
    int occ = (g_sums[(long long)idx * 8 + 7] != 0.0f) ? 1 : 0;
    unsigned m = __ballot_sync(0xffffffffu, occ);
    __shared__ int wt[32];
    if ((t & 31) == 0) wt[t >> 5] = __popc(m);
    __syncthreads();
    if (t < 32) {
        int v = wt[t];
        #pragma unroll
        for (int o = 16; o; o >>= 1) v += __shfl_down_sync(0xffffffffu, v, o);
        if (t == 0) g_blockSums[blockIdx.x] = v;
    }
}

// -------- K3b: ranks + direct head write (mean rows + coord rows) --------
__global__ void __launch_bounds__(SCAN_BLOCK)
k_head(float* __restrict__ out, int N) {
    const int t = threadIdx.x, bid = blockIdx.x;
    const int idx = bid * SCAN_BLOCK + t;
    const int lane = t & 31, warp = t >> 5;

    __shared__ int wt[32], wexcl[32], sBE;

    int occ = (g_sums[(long long)idx * 8 + 7] != 0.0f) ? 1 : 0;
    unsigned m = __ballot_sync(0xffffffffu, occ);
    if (lane == 0) wt[warp] = __popc(m);
    __syncthreads();

    if (warp == 0) {
        // scan the 32 warp totals
        int v = wt[lane], inc = v;
        #pragma unroll
        for (int o = 1; o < 32; o <<= 1) {
            int x = __shfl_up_sync(0xffffffffu, inc, o);
            if (lane >= o) inc += x;
        }
        wexcl[lane] = inc - v;
    } else if (warp == 1) {
        // scan the 256 block sums (8 per lane) to get this block's exclusive offset
        int vals[8]; int s = 0;
        #pragma unroll
        for (int k = 0; k < 8; k++) { vals[k] = g_blockSums[lane * 8 + k]; s += vals[k]; }
        int inc = s;
        #pragma unroll
        for (int o = 1; o < 32; o <<= 1) {
            int x = __shfl_up_sync(0xffffffffu, inc, o);
            if (lane >= o) inc += x;
        }
        int tot  = __shfl_sync(0xffffffffu, inc, 31);
        int lexc = inc - s;
        if (lane == (bid >> 3)) {
            int e = lexc;
            #pragma unroll
            for (int k = 0; k < 8; k++) if (k < (bid & 7)) e += vals[k];
            sBE = e;
        }
        if (lane == 0 && bid == 0) g_nuniq = tot;
    }
    __syncthreads();

    if (occ) {
        int r = sBE + wexcl[warp] + __popc(m & ((1u << lane) - 1u));
        const float* s = &g_sums[(long long)idx * 8];
        float inv = 1.0f / fmaxf(s[7], 1.0f);
        float* om = out + 7LL * r;
        #pragma unroll
        for (int f = 0; f < 7; f++) om[f] = s[f] * inv;
        float* ou = out + 7LL * N + 3LL * r;
        ou[0] = (float)(idx >> 12);
        ou[1] = (float)((idx >> 6) & 63);
        ou[2] = (float)(idx & 63);
    }
}

// -------- K4: sliver between n_unique and min(N, NVOX) (usually empty) --------
__global__ void __launch_bounds__(256)
k_sliver(float* __restrict__ out, int N, long long NM) {
    long long nu  = g_nuniq;
    long long n7  = 7LL * N;
    long long tid = (long long)blockIdx.x * 256 + threadIdx.x;
    long long nth = (long long)gridDim.x * 256;
    fill_span(out, 7LL * nu,      7LL * NM,      0.f, tid, nth);
    fill_span(out, n7 + 3LL * nu, n7 + 3LL * NM, -1.f, tid, nth);
}

extern "C" void kernel_launch(void* const* d_in, const int* in_sizes, int n_in,
                              void* d_out, int out_size) {
    const float* pts  = (const float*)d_in[0];
    const void*  grid = d_in[1];
    const int    N    = in_sizes[0] / 7;
    float*       out  = (float*)d_out;
    const long long NM = (N < NVOX) ? N : NVOX;   // upper bound on n_unique

    // 1. zero sums + dtype detect (extra block)
    k_init<<<ZBLK + 1, 256>>>((const unsigned int*)grid, 3LL * N);

    // 2. fused accumulate + guaranteed-tail fill, Bresenham-interleaved roles
    int A = (N + 255) / 256;
    int F = A / 3; if (F < 1) F = 1;
    k_acc_fill<<<A + F, 256>>>(pts, grid, N, A, F, out, NM);

    // 3. sorted-unique ranks + head rows
    k_scanA<<<SCAN_NBLOCKS, SCAN_BLOCK>>>();
    k_head<<<SCAN_NBLOCKS, SCAN_BLOCK>>>(out, N);

    // 4. sliver fill (depends on device-side n_unique; usually no-op)
    k_sliver<<<256, 256>>>(out, N, NM);
}

// round 12
// speedup vs baseline: 1.2049x; 1.1003x over previous
#include <cuda_runtime.h>
#include <cuda_bf16.h>
#include <stdint.h>

#define GRIDG 64
#define NVOX (GRIDG*GRIDG*GRIDG)            // 262144
#define HS_BLOCK 1024
#define HS_NBLOCKS (NVOX / HS_BLOCK)        // 256
#define AGG_FLAG (1 << 16)

// -------- device scratch (no allocation allowed) --------
__device__ float        g_sums[NVOX * 8];   // 7 feature sums + count (8 MB)
__device__ int          g_aggr[HS_NBLOCKS]; // per-block published cnt | FLAG
__device__ int          g_nuniq;
__device__ unsigned int g_sawOddNonzero = 0u;   // monotone: OR-only, idempotent

// -------- helpers --------
__device__ __forceinline__ void red_add_v4(float* addr, float a, float b, float c, float d) {
    asm volatile("red.global.add.v4.f32 [%0], {%1, %2, %3, %4};"
                 :: "l"(addr), "f"(a), "f"(b), "f"(c), "f"(d) : "memory");
}

// fill elements [lo, hi) of out with val; grid-stride over (tid, nth) lanes
__device__ __forceinline__ void fill_span(float* out, long long lo, long long hi,
                                          float val, long long tid, long long nth) {
    if (lo >= hi) return;
    long long alo = (lo + 3) & ~3LL; if (alo > hi) alo = hi;
    long long ahi = hi & ~3LL;       if (ahi < alo) ahi = alo;
    if (tid < (alo - lo)) out[lo + tid] = val;      // unaligned head (<4)
    if (tid < (hi - ahi)) out[ahi + tid] = val;     // unaligned tail (<4)
    long long n4 = (ahi - alo) >> 2;
    float4  v4 = make_float4(val, val, val, val);
    float4* p  = reinterpret_cast<float4*>(out + alo);
    for (long long k = tid; k < n4; k += nth) p[k] = v4;
}

// -------- K1: zero sums + aggr flags (+ dtype detect in the extra block) ----
#define ZBLK ((NVOX * 8 / 4 + 255) / 256)   // 2048
__global__ void __launch_bounds__(256)
k_init(const unsigned int* __restrict__ g, long long nwords) {
    if (blockIdx.x == ZBLK) {
        g_aggr[threadIdx.x] = 0;            // 256 flags, one per thread
        long long idx = (long long)threadIdx.x * 24694LL + 1LL; // odd words
        if (idx < nwords && g[idx] != 0u) atomicOr(&g_sawOddNonzero, 1u);
        return;
    }
    int i = blockIdx.x * 256 + threadIdx.x;
    reinterpret_cast<float4*>(g_sums)[i] = make_float4(0.f, 0.f, 0.f, 0.f);
}

// -------- K2: fused accumulate (SMEM-staged) + guaranteed-tail fill --------
__global__ void __launch_bounds__(256)
k_acc_fill(const float* __restrict__ pts, const void* __restrict__ grid,
           int N, int A, int F, float* __restrict__ out, long long NM) {
    const int bid = blockIdx.x;
    const long long T = (long long)A + F;
    const long long before = (long long)bid * F / T;         // fills before bid
    const bool is_fill = ((long long)(bid + 1) * F / T) > before;

    if (is_fill) {
        // guaranteed tail: [7*NM, 7N) = 0,  [7N+3*NM, 10N) = -1
        long long tid = before * 256 + threadIdx.x;
        long long nth = (long long)F * 256;
        long long n7  = 7LL * N;
        fill_span(out, 7LL * NM,      n7,       0.f, tid, nth);
        fill_span(out, n7 + 3LL * NM, 10LL * N, -1.f, tid, nth);
        return;
    }

    __shared__ float sp[256 * 7];   // 7168 B
    __shared__ int   si[256 * 6];   // 6144 B (int64 worst case)
    const int t      = threadIdx.x;
    const int acc_id = bid - (int)before;
    const int p0     = acc_id * 256;
    const int npts   = min(256, N - p0);
    const bool is64  = (g_sawOddNonzero == 0u);

    // stage points (coalesced float4 for full blocks)
    {
        const float* src = pts + (long long)p0 * 7;
        if (npts == 256) {
            const float4* s4 = reinterpret_cast<const float4*>(src);
            float4*       d4 = reinterpret_cast<float4*>(sp);
            #pragma unroll 2
            for (int k = t; k < 448; k += 256) d4[k] = s4[k];
        } else {
            for (int k = t; k < npts * 7; k += 256) sp[k] = src[k];
        }
    }
    // stage indices (coalesced int4 for full blocks)
    if (is64) {
        const int* src = (const int*)grid + (long long)p0 * 6;
        if (npts == 256) {
            const int4* s4 = reinterpret_cast<const int4*>(src);
            int4*       d4 = reinterpret_cast<int4*>(si);
            #pragma unroll 2
            for (int k = t; k < 384; k += 256) d4[k] = s4[k];
        } else {
            for (int k = t; k < npts * 6; k += 256) si[k] = src[k];
        }
    } else {
        const int* src = (const int*)grid + (long long)p0 * 3;
        if (npts == 256) {
            const int4* s4 = reinterpret_cast<const int4*>(src);
            int4*       d4 = reinterpret_cast<int4*>(si);
            for (int k = t; k < 192; k += 256) d4[k] = s4[k];
        } else {
            for (int k = t; k < npts * 3; k += 256) si[k] = src[k];
        }
    }
    __syncthreads();

    if (t < npts) {
        int g0, g1, g2;
        if (is64) { g0 = si[6*t]; g1 = si[6*t + 2]; g2 = si[6*t + 4]; }
        else      { g0 = si[3*t]; g1 = si[3*t + 1]; g2 = si[3*t + 2]; }
        int lin = (g0 * GRIDG + g1) * GRIDG + g2;
        const float* q = &sp[7 * t];
        float* s = &g_sums[(long long)lin * 8];
        red_add_v4(s,     q[0], q[1], q[2], q[3]);
        red_add_v4(s + 4, q[4], q[5], q[6], 1.0f);
    }
}

// -------- K3: single-pass scan + head write (decoupled aggregate chain) ----
// Each block: load its 1024-voxel slab once, publish its occupied count,
// sum predecessors' counts for its exclusive base, compact mean+coord rows
// into SMEM, and stream them out coalesced.
__global__ void __launch_bounds__(HS_BLOCK, 2)
k_headscan(float* __restrict__ out, int N) {
    __shared__ float slab[HS_BLOCK * 8];   // 32 KB: input rows, then mean staging
    __shared__ float sco[HS_BLOCK * 3];    // 12 KB: coord staging
    __shared__ int   sh[HS_NBLOCKS];       // predecessor aggregates
    __shared__ int   swx[32];              // warp exclusive offsets
    __shared__ int   sbase, stot;

    const int t = threadIdx.x, bid = blockIdx.x;
    const int lane = t & 31, warp = t >> 5;

    // 1. coalesced slab load (8192 floats = 2048 float4)
    const float4* src = reinterpret_cast<const float4*>(g_sums + (long long)bid * (HS_BLOCK * 8));
    float4* d4 = reinterpret_cast<float4*>(slab);
    d4[t] = src[t];
    d4[t + HS_BLOCK] = src[t + HS_BLOCK];
    __syncthreads();

    // 2. row into registers (frees slab for staging later)
    float4 ra = reinterpret_cast<float4*>(slab)[2 * t];
    float4 rb = reinterpret_cast<float4*>(slab)[2 * t + 1];
    int occ = (rb.w != 0.0f) ? 1 : 0;
    unsigned m = __ballot_sync(0xffffffffu, occ);
    if (lane == 0) swx[warp] = __popc(m);
    __syncthreads();

    // 3. warp 0: scan 32 warp counts, publish block total
    if (warp == 0) {
        int v = swx[lane], inc = v;
        #pragma unroll
        for (int o = 1; o < 32; o <<= 1) {
            int x = __shfl_up_sync(0xffffffffu, inc, o);
            if (lane >= o) inc += x;
        }
        int tot = __shfl_sync(0xffffffffu, inc, 31);
        swx[lane] = inc - v;               // exclusive warp offsets
        if (lane == 0) {
            stot = tot;
            atomicExch(&g_aggr[bid], tot | AGG_FLAG);
        }
    }
    // 4. spin on predecessors' aggregates (all blocks co-resident)
    if (t < bid) {
        int v;
        do { v = *(volatile int*)&g_aggr[t]; } while (!(v & AGG_FLAG));
        sh[t] = v & 0xFFFF;
    }
    if (t == 0) sbase = 0;
    __syncthreads();
    {   // reduce sh[0..bid) into sbase
        int part = (t < bid) ? sh[t] : 0;
        #pragma unroll
        for (int o = 16; o; o >>= 1) part += __shfl_down_sync(0xffffffffu, part, o);
        if (lane == 0 && part) atomicAdd(&sbase, part);
    }
    __syncthreads();
    const int base = sbase, tot = stot;
    if (bid == HS_NBLOCKS - 1 && t == 0) g_nuniq = base + tot;

    // 5. compact into SMEM staging
    if (occ) {
        int rl = swx[warp] + __popc(m & ((1u << lane) - 1u));   // local rank
        float inv = 1.0f / fmaxf(rb.w, 1.0f);
        float* om = &slab[7 * rl];
        om[0] = ra.x * inv; om[1] = ra.y * inv; om[2] = ra.z * inv; om[3] = ra.w * inv;
        om[4] = rb.x * inv; om[5] = rb.y * inv; om[6] = rb.z * inv;
        int idx = bid * HS_BLOCK + t;
        sco[3 * rl]     = (float)(idx >> 12);
        sco[3 * rl + 1] = (float)((idx >> 6) & 63);
        sco[3 * rl + 2] = (float)(idx & 63);
    }
    __syncthreads();

    // 6. coalesced streams out
    float* om = out + 7LL * base;
    for (int k = t; k < 7 * tot; k += HS_BLOCK) om[k] = slab[k];
    float* ou = out + 7LL * N + 3LL * base;
    for (int k = t; k < 3 * tot; k += HS_BLOCK) ou[k] = sco[k];
}

// -------- K4: sliver between n_unique and min(N, NVOX) (usually empty) ----
__global__ void __launch_bounds__(256)
k_sliver(float* __restrict__ out, int N, long long NM) {
    long long nu  = g_nuniq;
    long long n7  = 7LL * N;
    long long tid = (long long)blockIdx.x * 256 + threadIdx.x;
    long long nth = (long long)gridDim.x * 256;
    fill_span(out, 7LL * nu,      7LL * NM,      0.f, tid, nth);
    fill_span(out, n7 + 3LL * nu, n7 + 3LL * NM, -1.f, tid, nth);
}

extern "C" void kernel_launch(void* const* d_in, const int* in_sizes, int n_in,
                              void* d_out, int out_size) {
    const float* pts  = (const float*)d_in[0];
    const void*  grid = d_in[1];
    const int    N    = in_sizes[0] / 7;
    float*       out  = (float*)d_out;
    const long long NM = (N < NVOX) ? N : NVOX;   // upper bound on n_unique

    // 1. zero sums + aggr flags + dtype detect (extra block)
    k_init<<<ZBLK + 1, 256>>>((const unsigned int*)grid, 3LL * N);

    // 2. fused accumulate + guaranteed-tail fill, Bresenham-interleaved roles
    int A = (N + 255) / 256;
    int F = A / 3; if (F < 1) F = 1;
    k_acc_fill<<<A + F, 256>>>(pts, grid, N, A, F, out, NM);

    // 3. single-pass scan + head rows
    k_headscan<<<HS_NBLOCKS, HS_BLOCK>>>(out, N);

    // 4. sliver fill (depends on device-side n_unique; usually no-op)
    k_sliver<<<256, 256>>>(out, N, NM);
}

// round 14
// speedup vs baseline: 1.2255x; 1.0171x over previous
#include <cuda_runtime.h>
#include <cuda_bf16.h>
#include <stdint.h>

#define GRIDG 64
#define NVOX (GRIDG*GRIDG*GRIDG)            // 262144
#define HS_BLOCK 1024
#define HS_NBLOCKS (NVOX / HS_BLOCK)        // 256
#define AGG_FLAG (1 << 16)

// -------- device scratch (no allocation allowed) --------
__device__ float        g_sums[NVOX * 8];   // 7 feature sums + count (8 MB)
__device__ int          g_aggr[HS_NBLOCKS]; // per-block published cnt | FLAG
__device__ int          g_nuniq;
__device__ unsigned int g_sawOddNonzero = 0u;   // monotone: OR-only, idempotent

// -------- helpers --------
__device__ __forceinline__ void red_add_v4(float* addr, float a, float b, float c, float d) {
    asm volatile("red.global.add.v4.f32 [%0], {%1, %2, %3, %4};"
                 :: "l"(addr), "f"(a), "f"(b), "f"(c), "f"(d) : "memory");
}

// fill elements [lo, hi) of out with val; grid-stride over (tid, nth) lanes.
// Uses evict-first (.cs) stores so the bulk fill does not evict the g_sums
// atomic working set from L2 while accumulate blocks run concurrently.
__device__ __forceinline__ void fill_span(float* out, long long lo, long long hi,
                                          float val, long long tid, long long nth) {
    if (lo >= hi) return;
    long long alo = (lo + 3) & ~3LL; if (alo > hi) alo = hi;
    long long ahi = hi & ~3LL;       if (ahi < alo) ahi = alo;
    if (tid < (alo - lo)) out[lo + tid] = val;      // unaligned head (<4)
    if (tid < (hi - ahi)) out[ahi + tid] = val;     // unaligned tail (<4)
    long long n4 = (ahi - alo) >> 2;
    float4  v4 = make_float4(val, val, val, val);
    float4* p  = reinterpret_cast<float4*>(out + alo);
    for (long long k = tid; k < n4; k += nth) __stcs(&p[k], v4);
}

// -------- K1: zero sums + aggr flags (+ dtype detect in the extra block) ----
#define ZBLK ((NVOX * 8 / 4 + 255) / 256)   // 2048
__global__ void __launch_bounds__(256)
k_init(const unsigned int* __restrict__ g, long long nwords) {
    if (blockIdx.x == ZBLK) {
        g_aggr[threadIdx.x] = 0;            // 256 flags, one per thread
        long long idx = (long long)threadIdx.x * 24694LL + 1LL; // odd words
        if (idx < nwords && g[idx] != 0u) atomicOr(&g_sawOddNonzero, 1u);
        return;
    }
    int i = blockIdx.x * 256 + threadIdx.x;
    reinterpret_cast<float4*>(g_sums)[i] = make_float4(0.f, 0.f, 0.f, 0.f);
}

// -------- K2: fused accumulate (SMEM-staged) + guaranteed-tail fill --------
__global__ void __launch_bounds__(256)
k_acc_fill(const float* __restrict__ pts, const void* __restrict__ grid,
           int N, int A, int F, float* __restrict__ out, long long NM) {
    const int bid = blockIdx.x;
    const long long T = (long long)A + F;
    const long long before = (long long)bid * F / T;         // fills before bid
    const bool is_fill = ((long long)(bid + 1) * F / T) > before;

    if (is_fill) {
        // guaranteed tail: [7*NM, 7N) = 0,  [7N+3*NM, 10N) = -1
        long long tid = before * 256 + threadIdx.x;
        long long nth = (long long)F * 256;
        long long n7  = 7LL * N;
        fill_span(out, 7LL * NM,      n7,       0.f, tid, nth);
        fill_span(out, n7 + 3LL * NM, 10LL * N, -1.f, tid, nth);
        return;
    }

    __shared__ float sp[256 * 7];   // 7168 B
    __shared__ int   si[256 * 6];   // 6144 B (int64 worst case)
    const int t      = threadIdx.x;
    const int acc_id = bid - (int)before;
    const int p0     = acc_id * 256;
    const int npts   = min(256, N - p0);
    const bool is64  = (g_sawOddNonzero == 0u);

    // stage points (coalesced float4 for full blocks)
    {
        const float* src = pts + (long long)p0 * 7;
        if (npts == 256) {
            const float4* s4 = reinterpret_cast<const float4*>(src);
            float4*       d4 = reinterpret_cast<float4*>(sp);
            #pragma unroll 2
            for (int k = t; k < 448; k += 256) d4[k] = s4[k];
        } else {
            for (int k = t; k < npts * 7; k += 256) sp[k] = src[k];
        }
    }
    // stage indices (coalesced int4 for full blocks)
    if (is64) {
        const int* src = (const int*)grid + (long long)p0 * 6;
        if (npts == 256) {
            const int4* s4 = reinterpret_cast<const int4*>(src);
            int4*       d4 = reinterpret_cast<int4*>(si);
            #pragma unroll 2
            for (int k = t; k < 384; k += 256) d4[k] = s4[k];
        } else {
            for (int k = t; k < npts * 6; k += 256) si[k] = src[k];
        }
    } else {
        const int* src = (const int*)grid + (long long)p0 * 3;
        if (npts == 256) {
            const int4* s4 = reinterpret_cast<const int4*>(src);
            int4*       d4 = reinterpret_cast<int4*>(si);
            for (int k = t; k < 192; k += 256) d4[k] = s4[k];
        } else {
            for (int k = t; k < npts * 3; k += 256) si[k] = src[k];
        }
    }
    __syncthreads();

    if (t < npts) {
        int g0, g1, g2;
        if (is64) { g0 = si[6*t]; g1 = si[6*t + 2]; g2 = si[6*t + 4]; }
        else      { g0 = si[3*t]; g1 = si[3*t + 1]; g2 = si[3*t + 2]; }
        int lin = (g0 * GRIDG + g1) * GRIDG + g2;
        const float* q = &sp[7 * t];
        float* s = &g_sums[(long long)lin * 8];
        red_add_v4(s,     q[0], q[1], q[2], q[3]);
        red_add_v4(s + 4, q[4], q[5], q[6], 1.0f);
    }
}

// -------- K3: single-pass scan + head write + sliver (decoupled chain) ----
// Each block: load its 1024-voxel slab once, publish its occupied count,
// sum predecessors' counts for its exclusive base, compact mean+coord rows
// into SMEM, stream them out coalesced. Block 255 additionally fills the
// sliver [7*nu, 7*NM) / [7N+3*nu, 7N+3*NM) (expected empty).
__global__ void __launch_bounds__(HS_BLOCK, 2)
k_headscan(float* __restrict__ out, int N, long long NM) {
    __shared__ float slab[HS_BLOCK * 8];   // 32 KB: input rows, then mean staging
    __shared__ float sco[HS_BLOCK * 3];    // 12 KB: coord staging
    __shared__ int   sh[HS_NBLOCKS];       // predecessor aggregates
    __shared__ int   swx[32];              // warp exclusive offsets
    __shared__ int   sbase, stot;

    const int t = threadIdx.x, bid = blockIdx.x;
    const int lane = t & 31, warp = t >> 5;

    // 1. coalesced slab load (8192 floats = 2048 float4)
    const float4* src = reinterpret_cast<const float4*>(g_sums + (long long)bid * (HS_BLOCK * 8));
    float4* d4 = reinterpret_cast<float4*>(slab);
    d4[t] = src[t];
    d4[t + HS_BLOCK] = src[t + HS_BLOCK];
    __syncthreads();

    // 2. row into registers (frees slab for staging later)
    float4 ra = reinterpret_cast<float4*>(slab)[2 * t];
    float4 rb = reinterpret_cast<float4*>(slab)[2 * t + 1];
    int occ = (rb.w != 0.0f) ? 1 : 0;
    unsigned m = __ballot_sync(0xffffffffu, occ);
    if (lane == 0) swx[warp] = __popc(m);
    __syncthreads();

    // 3. warp 0: scan 32 warp counts, publish block total
    if (warp == 0) {
        int v = swx[lane], inc = v;
        #pragma unroll
        for (int o = 1; o < 32; o <<= 1) {
            int x = __shfl_up_sync(0xffffffffu, inc, o);
            if (lane >= o) inc += x;
        }
        int tot = __shfl_sync(0xffffffffu, inc, 31);
        swx[lane] = inc - v;               // exclusive warp offsets
        if (lane == 0) {
            stot = tot;
            atomicExch(&g_aggr[bid], tot | AGG_FLAG);
        }
    }
    // 4. spin on predecessors' aggregates (all 256 blocks co-resident:
    //    45.3 KB smem x 2 blocks/SM x 148 SMs = 296 >= 256)
    if (t < bid) {
        int v;
        do { v = *(volatile int*)&g_aggr[t]; } while (!(v & AGG_FLAG));
        sh[t] = v & 0xFFFF;
    }
    if (t == 0) sbase = 0;
    __syncthreads();
    {   // reduce sh[0..bid) into sbase
        int part = (t < bid) ? sh[t] : 0;
        #pragma unroll
        for (int o = 16; o; o >>= 1) part += __shfl_down_sync(0xffffffffu, part, o);
        if (lane == 0 && part) atomicAdd(&sbase, part);
    }
    __syncthreads();
    const int base = sbase, tot = stot;

    // 5. compact into SMEM staging
    if (occ) {
        int rl = swx[warp] + __popc(m & ((1u << lane) - 1u));   // local rank
        float inv = 1.0f / fmaxf(rb.w, 1.0f);
        float* om = &slab[7 * rl];
        om[0] = ra.x * inv; om[1] = ra.y * inv; om[2] = ra.z * inv; om[3] = ra.w * inv;
        om[4] = rb.x * inv; om[5] = rb.y * inv; om[6] = rb.z * inv;
        int idx = bid * HS_BLOCK + t;
        sco[3 * rl]     = (float)(idx >> 12);
        sco[3 * rl + 1] = (float)((idx >> 6) & 63);
        sco[3 * rl + 2] = (float)(idx & 63);
    }
    __syncthreads();

    // 6. coalesced streams out
    float* om = out + 7LL * base;
    for (int k = t; k < 7 * tot; k += HS_BLOCK) om[k] = slab[k];
    float* ou = out + 7LL * N + 3LL * base;
    for (int k = t; k < 3 * tot; k += HS_BLOCK) ou[k] = sco[k];

    // 7. block 255 knows n_unique = base + tot: record it and fill the
    //    sliver up to NM (expected empty; pathological cases stay correct).
    if (bid == HS_NBLOCKS - 1) {
        long long nu = (long long)base + tot;
        if (t == 0) g_nuniq = (int)nu;
        long long n7 = 7LL * N;
        fill_span(out, 7LL * nu,      7LL * NM,      0.f, t, HS_BLOCK);
        fill_span(out, n7 + 3LL * nu, n7 + 3LL * NM, -1.f, t, HS_BLOCK);
    }
}

extern "C" void kernel_launch(void* const* d_in, const int* in_sizes, int n_in,
                              void* d_out, int out_size) {
    const float* pts  = (const float*)d_in[0];
    const void*  grid = d_in[1];
    const int    N    = in_sizes[0] / 7;
    float*       out  = (float*)d_out;
    const long long NM = (N < NVOX) ? N : NVOX;   // upper bound on n_unique

    // 1. zero sums + aggr flags + dtype detect (extra block)
    k_init<<<ZBLK + 1, 256>>>((const unsigned int*)grid, 3LL * N);

    // 2. fused accumulate + guaranteed-tail fill, Bresenham-interleaved roles
    int A = (N + 255) / 256;
    int F = A / 3; if (F < 1) F = 1;
    k_acc_fill<<<A + F, 256>>>(pts, grid, N, A, F, out, NM);

    // 3. single-pass scan + head rows + sliver
    k_headscan<<<HS_NBLOCKS, HS_BLOCK>>>(out, N, NM);
}

// round 15
// speedup vs baseline: 1.2294x; 1.0032x over previous
#include <cuda_runtime.h>
#include <cuda_bf16.h>
#include <stdint.h>

#define GRIDG 64
#define NVOX (GRIDG*GRIDG*GRIDG)            // 262144
#define HS_BLOCK 1024
#define HS_NBLOCKS (NVOX / HS_BLOCK)        // 256
#define AGG_FLAG (1 << 16)

// -------- device scratch (no allocation allowed) --------
// NOTE: g_sums starts zeroed (module load) and is re-zeroed by k_headscan at
// the end of every call, so no bulk-zero kernel is needed.
__device__ float        g_sums[NVOX * 8];   // 7 feature sums + count (8 MB)
__device__ int          g_aggr[HS_NBLOCKS]; // per-block published cnt | FLAG
__device__ int          g_nuniq;
__device__ unsigned int g_sawOddNonzero = 0u;   // monotone: OR-only, idempotent

// -------- helpers --------
__device__ __forceinline__ void red_add_v4(float* addr, float a, float b, float c, float d) {
    asm volatile("red.global.add.v4.f32 [%0], {%1, %2, %3, %4};"
                 :: "l"(addr), "f"(a), "f"(b), "f"(c), "f"(d) : "memory");
}

// fill elements [lo, hi) of out with val; grid-stride over (tid, nth) lanes.
// Uses evict-first (.cs) stores so the bulk fill does not evict the g_sums
// atomic working set from L2 while accumulate blocks run concurrently.
__device__ __forceinline__ void fill_span(float* out, long long lo, long long hi,
                                          float val, long long tid, long long nth) {
    if (lo >= hi) return;
    long long alo = (lo + 3) & ~3LL; if (alo > hi) alo = hi;
    long long ahi = hi & ~3LL;       if (ahi < alo) ahi = alo;
    if (tid < (alo - lo)) out[lo + tid] = val;      // unaligned head (<4)
    if (tid < (hi - ahi)) out[ahi + tid] = val;     // unaligned tail (<4)
    long long n4 = (ahi - alo) >> 2;
    float4  v4 = make_float4(val, val, val, val);
    float4* p  = reinterpret_cast<float4*>(out + alo);
    for (long long k = tid; k < n4; k += nth) __stcs(&p[k], v4);
}

// -------- K1: single block — zero aggr flags + dtype detect --------
// Detect: odd 32-bit words of grid_ind all zero => int64 (high words);
// any nonzero => int32 coords.
__global__ void __launch_bounds__(256)
k_init(const unsigned int* __restrict__ g, long long nwords) {
    g_aggr[threadIdx.x] = 0;
    long long idx = (long long)threadIdx.x * 24694LL + 1LL; // odd words
    if (idx < nwords && g[idx] != 0u) atomicOr(&g_sawOddNonzero, 1u);
}

// -------- K2: fused accumulate (SMEM-staged) + guaranteed-tail fill --------
__global__ void __launch_bounds__(256)
k_acc_fill(const float* __restrict__ pts, const void* __restrict__ grid,
           int N, int A, int F, float* __restrict__ out, long long NM) {
    const int bid = blockIdx.x;
    const long long T = (long long)A + F;
    const long long before = (long long)bid * F / T;         // fills before bid
    const bool is_fill = ((long long)(bid + 1) * F / T) > before;

    if (is_fill) {
        // guaranteed tail: [7*NM, 7N) = 0,  [7N+3*NM, 10N) = -1
        long long tid = before * 256 + threadIdx.x;
        long long nth = (long long)F * 256;
        long long n7  = 7LL * N;
        fill_span(out, 7LL * NM,      n7,       0.f, tid, nth);
        fill_span(out, n7 + 3LL * NM, 10LL * N, -1.f, tid, nth);
        return;
    }

    __shared__ float sp[256 * 7];   // 7168 B
    __shared__ int   si[256 * 6];   // 6144 B (int64 worst case)
    const int t      = threadIdx.x;
    const int acc_id = bid - (int)before;
    const int p0     = acc_id * 256;
    const int npts   = min(256, N - p0);
    const bool is64  = (g_sawOddNonzero == 0u);

    // stage points (coalesced float4 for full blocks)
    {
        const float* src = pts + (long long)p0 * 7;
        if (npts == 256) {
            const float4* s4 = reinterpret_cast<const float4*>(src);
            float4*       d4 = reinterpret_cast<float4*>(sp);
            #pragma unroll 2
            for (int k = t; k < 448; k += 256) d4[k] = s4[k];
        } else {
            for (int k = t; k < npts * 7; k += 256) sp[k] = src[k];
        }
    }
    // stage indices (coalesced int4 for full blocks)
    if (is64) {
        const int* src = (const int*)grid + (long long)p0 * 6;
        if (npts == 256) {
            const int4* s4 = reinterpret_cast<const int4*>(src);
            int4*       d4 = reinterpret_cast<int4*>(si);
            #pragma unroll 2
            for (int k = t; k < 384; k += 256) d4[k] = s4[k];
        } else {
            for (int k = t; k < npts * 6; k += 256) si[k] = src[k];
        }
    } else {
        const int* src = (const int*)grid + (long long)p0 * 3;
        if (npts == 256) {
            const int4* s4 = reinterpret_cast<const int4*>(src);
            int4*       d4 = reinterpret_cast<int4*>(si);
            for (int k = t; k < 192; k += 256) d4[k] = s4[k];
        } else {
            for (int k = t; k < npts * 3; k += 256) si[k] = src[k];
        }
    }
    __syncthreads();

    if (t < npts) {
        int g0, g1, g2;
        if (is64) { g0 = si[6*t]; g1 = si[6*t + 2]; g2 = si[6*t + 4]; }
        else      { g0 = si[3*t]; g1 = si[3*t + 1]; g2 = si[3*t + 2]; }
        int lin = (g0 * GRIDG + g1) * GRIDG + g2;
        const float* q = &sp[7 * t];
        float* s = &g_sums[(long long)lin * 8];
        red_add_v4(s,     q[0], q[1], q[2], q[3]);
        red_add_v4(s + 4, q[4], q[5], q[6], 1.0f);
    }
}

// -------- K3: single-pass scan + head write + sliver + sums-rezero --------
// Each block: load its 1024-voxel slab once, zero it back (next call's init),
// publish its occupied count, sum predecessors' counts for its exclusive
// base, compact mean+coord rows into SMEM, stream them out coalesced.
// Block 255 additionally fills the sliver (expected empty).
__global__ void __launch_bounds__(HS_BLOCK, 2)
k_headscan(float* __restrict__ out, int N, long long NM) {
    __shared__ float slab[HS_BLOCK * 8];   // 32 KB: input rows, then mean staging
    __shared__ float sco[HS_BLOCK * 3];    // 12 KB: coord staging
    __shared__ int   sh[HS_NBLOCKS];       // predecessor aggregates
    __shared__ int   swx[32];              // warp exclusive offsets
    __shared__ int   sbase, stot;

    const int t = threadIdx.x, bid = blockIdx.x;
    const int lane = t & 31, warp = t >> 5;

    // 1. coalesced slab load (8192 floats = 2048 float4)
    float4* src = reinterpret_cast<float4*>(g_sums + (long long)bid * (HS_BLOCK * 8));
    float4* d4 = reinterpret_cast<float4*>(slab);
    d4[t] = src[t];
    d4[t + HS_BLOCK] = src[t + HS_BLOCK];
    __syncthreads();

    // 2. row into registers (frees slab for staging later)
    float4 ra = reinterpret_cast<float4*>(slab)[2 * t];
    float4 rb = reinterpret_cast<float4*>(slab)[2 * t + 1];

    // 2b. zero back our own gmem slab for the next invocation (lines stay
    //     L2-resident-dirty so next call's RED atomics hit in L2).
    {
        float4 z4 = make_float4(0.f, 0.f, 0.f, 0.f);
        src[t] = z4;
        src[t + HS_BLOCK] = z4;
    }

    int occ = (rb.w != 0.0f) ? 1 : 0;
    unsigned m = __ballot_sync(0xffffffffu, occ);
    if (lane == 0) swx[warp] = __popc(m);
    __syncthreads();

    // 3. warp 0: scan 32 warp counts, publish block total
    if (warp == 0) {
        int v = swx[lane], inc = v;
        #pragma unroll
        for (int o = 1; o < 32; o <<= 1) {
            int x = __shfl_up_sync(0xffffffffu, inc, o);
            if (lane >= o) inc += x;
        }
        int tot = __shfl_sync(0xffffffffu, inc, 31);
        swx[lane] = inc - v;               // exclusive warp offsets
        if (lane == 0) {
            stot = tot;
            atomicExch(&g_aggr[bid], tot | AGG_FLAG);
        }
    }
    // 4. spin on predecessors' aggregates (all 256 blocks co-resident:
    //    45.3 KB smem x 2 blocks/SM x 148 SMs = 296 >= 256)
    if (t < bid) {
        int v;
        do { v = *(volatile int*)&g_aggr[t]; } while (!(v & AGG_FLAG));
        sh[t] = v & 0xFFFF;
    }
    if (t == 0) sbase = 0;
    __syncthreads();
    {   // reduce sh[0..bid) into sbase
        int part = (t < bid) ? sh[t] : 0;
        #pragma unroll
        for (int o = 16; o; o >>= 1) part += __shfl_down_sync(0xffffffffu, part, o);
        if (lane == 0 && part) atomicAdd(&sbase, part);
    }
    __syncthreads();
    const int base = sbase, tot = stot;

    // 5. compact into SMEM staging
    if (occ) {
        int rl = swx[warp] + __popc(m & ((1u << lane) - 1u));   // local rank
        float inv = 1.0f / fmaxf(rb.w, 1.0f);
        float* om = &slab[7 * rl];
        om[0] = ra.x * inv; om[1] = ra.y * inv; om[2] = ra.z * inv; om[3] = ra.w * inv;
        om[4] = rb.x * inv; om[5] = rb.y * inv; om[6] = rb.z * inv;
        int idx = bid * HS_BLOCK + t;
        sco[3 * rl]     = (float)(idx >> 12);
        sco[3 * rl + 1] = (float)((idx >> 6) & 63);
        sco[3 * rl + 2] = (float)(idx & 63);
    }
    __syncthreads();

    // 6. coalesced streams out
    float* om = out + 7LL * base;
    for (int k = t; k < 7 * tot; k += HS_BLOCK) om[k] = slab[k];
    float* ou = out + 7LL * N + 3LL * base;
    for (int k = t; k < 3 * tot; k += HS_BLOCK) ou[k] = sco[k];

    // 7. block 255 knows n_unique = base + tot: record it and fill the
    //    sliver up to NM (expected empty; pathological cases stay correct).
    if (bid == HS_NBLOCKS - 1) {
        long long nu = (long long)base + tot;
        if (t == 0) g_nuniq = (int)nu;
        long long n7 = 7LL * N;
        fill_span(out, 7LL * nu,      7LL * NM,      0.f, t, HS_BLOCK);
        fill_span(out, n7 + 3LL * nu, n7 + 3LL * NM, -1.f, t, HS_BLOCK);
    }
}

extern "C" void kernel_launch(void* const* d_in, const int* in_sizes, int n_in,
                              void* d_out, int out_size) {
    const float* pts  = (const float*)d_in[0];
    const void*  grid = d_in[1];
    const int    N    = in_sizes[0] / 7;
    float*       out  = (float*)d_out;
    const long long NM = (N < NVOX) ? N : NVOX;   // upper bound on n_unique

    // 1. zero aggr flags + dtype detect (single block; g_sums is kept zeroed
    //    across calls by k_headscan)
    k_init<<<1, 256>>>((const unsigned int*)grid, 3LL * N);

    // 2. fused accumulate + guaranteed-tail fill, Bresenham-interleaved roles
    int A = (N + 255) / 256;
    int F = A / 3; if (F < 1) F = 1;
    k_acc_fill<<<A + F, 256>>>(pts, grid, N, A, F, out, NM);

    // 3. single-pass scan + head rows + sliver + sums re-zero
    k_headscan<<<HS_NBLOCKS, HS_BLOCK>>>(out, N, NM);
}

// round 17
// speedup vs baseline: 1.2358x; 1.0052x over previous
#include <cuda_runtime.h>
#include <cuda_bf16.h>
#include <stdint.h>

#define GRIDG 64
#define NVOX (GRIDG*GRIDG*GRIDG)            // 262144
#define HS_BLOCK 1024
#define HS_NBLOCKS (NVOX / HS_BLOCK)        // 256
#define AGG_FLAG (1 << 16)

// -------- device scratch (no allocation allowed) --------
// g_sums starts zeroed (module load) and is re-zeroed by k_headscan at the
// end of every call, so no bulk-zero kernel is needed. g_aggr is zeroed by
// the first fill block of k_acc_fill each call.
__device__ float g_sums[NVOX * 8];   // 7 feature sums + count (8 MB)
__device__ int   g_aggr[HS_NBLOCKS]; // per-block published cnt | FLAG
__device__ int   g_nuniq;

// -------- helpers --------
__device__ __forceinline__ void red_add_v4(float* addr, float a, float b, float c, float d) {
    asm volatile("red.global.add.v4.f32 [%0], {%1, %2, %3, %4};"
                 :: "l"(addr), "f"(a), "f"(b), "f"(c), "f"(d) : "memory");
}

// fill elements [lo, hi) of out with val; grid-stride over (tid, nth) lanes.
// Evict-first (.cs) stores keep the g_sums atomic working set L2-resident
// while accumulate blocks run concurrently.
__device__ __forceinline__ void fill_span(float* out, long long lo, long long hi,
                                          float val, long long tid, long long nth) {
    if (lo >= hi) return;
    long long alo = (lo + 3) & ~3LL; if (alo > hi) alo = hi;
    long long ahi = hi & ~3LL;       if (ahi < alo) ahi = alo;
    if (tid < (alo - lo)) out[lo + tid] = val;      // unaligned head (<4)
    if (tid < (hi - ahi)) out[ahi + tid] = val;     // unaligned tail (<4)
    long long n4 = (ahi - alo) >> 2;
    float4  v4 = make_float4(val, val, val, val);
    float4* p  = reinterpret_cast<float4*>(out + alo);
    for (long long k = tid; k < n4; k += nth) __stcs(&p[k], v4);
}

// -------- K1: fused accumulate (SMEM-staged) + guaranteed-tail fill --------
// Block-local dtype detection: sample 8 fixed odd 32-bit words of grid_ind
// (L2-broadcast). All zero => int64 (high words); any nonzero => int32
// (P(false|int32) = 64^-8).
__global__ void __launch_bounds__(256)
k_acc_fill(const float* __restrict__ pts, const void* __restrict__ grid,
           int N, int A, int F, float* __restrict__ out, long long NM) {
    const int bid = blockIdx.x;
    const int t   = threadIdx.x;
    const long long T = (long long)A + F;
    const long long before = (long long)bid * F / T;         // fills before bid
    const bool is_fill = ((long long)(bid + 1) * F / T) > before;

    if (is_fill) {
        // first fill block zeroes the aggregate flags for k_headscan
        if (before == 0) g_aggr[t] = 0;
        // guaranteed tail: [7*NM, 7N) = 0,  [7N+3*NM, 10N) = -1
        long long tid = before * 256 + t;
        long long nth = (long long)F * 256;
        long long n7  = 7LL * N;
        fill_span(out, 7LL * NM,      n7,       0.f, tid, nth);
        fill_span(out, n7 + 3LL * NM, 10LL * N, -1.f, tid, nth);
        return;
    }

    __shared__ float sp[256 * 7];   // 7168 B
    __shared__ int   si[256 * 6];   // 6144 B (int64 worst case)
    __shared__ int   s_is32;
    const int acc_id = bid - (int)before;
    const int p0     = acc_id * 256;
    const int npts   = min(256, N - p0);

    // block-local dtype detection (8 sampled odd words)
    if (t == 0) s_is32 = 0;
    __syncthreads();
    if (t < 8) {
        long long idx = 2LL * t + 1;               // odd words 1..15
        if (idx < 3LL * N) {                       // 3N = minimum word count
            if (((const unsigned int*)grid)[idx] != 0u) atomicOr(&s_is32, 1);
        }
    }
    __syncthreads();
    const bool is64 = (s_is32 == 0);

    // stage points (coalesced float4 for full blocks)
    {
        const float* src = pts + (long long)p0 * 7;
        if (npts == 256) {
            const float4* s4 = reinterpret_cast<const float4*>(src);
            float4*       d4 = reinterpret_cast<float4*>(sp);
            #pragma unroll 2
            for (int k = t; k < 448; k += 256) d4[k] = s4[k];
        } else {
            for (int k = t; k < npts * 7; k += 256) sp[k] = src[k];
        }
    }
    // stage indices (coalesced int4 for full blocks)
    if (is64) {
        const int* src = (const int*)grid + (long long)p0 * 6;
        if (npts == 256) {
            const int4* s4 = reinterpret_cast<const int4*>(src);
            int4*       d4 = reinterpret_cast<int4*>(si);
            #pragma unroll 2
            for (int k = t; k < 384; k += 256) d4[k] = s4[k];
        } else {
            for (int k = t; k < npts * 6; k += 256) si[k] = src[k];
        }
    } else {
        const int* src = (const int*)grid + (long long)p0 * 3;
        if (npts == 256) {
            const int4* s4 = reinterpret_cast<const int4*>(src);
            int4*       d4 = reinterpret_cast<int4*>(si);
            for (int k = t; k < 192; k += 256) d4[k] = s4[k];
        } else {
            for (int k = t; k < npts * 3; k += 256) si[k] = src[k];
        }
    }
    __syncthreads();

    if (t < npts) {
        int g0, g1, g2;
        if (is64) { g0 = si[6*t]; g1 = si[6*t + 2]; g2 = si[6*t + 4]; }
        else      { g0 = si[3*t]; g1 = si[3*t + 1]; g2 = si[3*t + 2]; }
        int lin = (g0 * GRIDG + g1) * GRIDG + g2;
        const float* q = &sp[7 * t];
        float* s = &g_sums[(long long)lin * 8];
        red_add_v4(s,     q[0], q[1], q[2], q[3]);
        red_add_v4(s + 4, q[4], q[5], q[6], 1.0f);
    }
}

// -------- K2: single-pass scan + head write + sliver + sums-rezero --------
// Each block: load its 1024-voxel slab once, zero it back (next call's init),
// publish its occupied count, sum predecessors' counts for its exclusive
// base, compact mean+coord rows into SMEM, stream them out coalesced.
// Block 255 additionally fills the sliver (expected empty).
__global__ void __launch_bounds__(HS_BLOCK, 2)
k_headscan(float* __restrict__ out, int N, long long NM) {
    __shared__ float slab[HS_BLOCK * 8];   // 32 KB: input rows, then mean staging
    __shared__ float sco[HS_BLOCK * 3];    // 12 KB: coord staging
    __shared__ int   sh[HS_NBLOCKS];       // predecessor aggregates
    __shared__ int   swx[32];              // warp exclusive offsets
    __shared__ int   sbase, stot;

    const int t = threadIdx.x, bid = blockIdx.x;
    const int lane = t & 31, warp = t >> 5;

    // 1. coalesced slab load (8192 floats = 2048 float4)
    float4* src = reinterpret_cast<float4*>(g_sums + (long long)bid * (HS_BLOCK * 8));
    float4* d4 = reinterpret_cast<float4*>(slab);
    d4[t] = src[t];
    d4[t + HS_BLOCK] = src[t + HS_BLOCK];
    __syncthreads();

    // 2. row into registers (frees slab for staging later)
    float4 ra = reinterpret_cast<float4*>(slab)[2 * t];
    float4 rb = reinterpret_cast<float4*>(slab)[2 * t + 1];

    // 2b. zero back our own gmem slab for the next invocation (lines stay
    //     L2-resident-dirty so next call's RED atomics hit in L2).
    {
        float4 z4 = make_float4(0.f, 0.f, 0.f, 0.f);
        src[t] = z4;
        src[t + HS_BLOCK] = z4;
    }

    int occ = (rb.w != 0.0f) ? 1 : 0;
    unsigned m = __ballot_sync(0xffffffffu, occ);
    if (lane == 0) swx[warp] = __popc(m);
    __syncthreads();

    // 3. warp 0: scan 32 warp counts, publish block total
    if (warp == 0) {
        int v = swx[lane], inc = v;
        #pragma unroll
        for (int o = 1; o < 32; o <<= 1) {
            int x = __shfl_up_sync(0xffffffffu, inc, o);
            if (lane >= o) inc += x;
        }
        int tot = __shfl_sync(0xffffffffu, inc, 31);
        swx[lane] = inc - v;               // exclusive warp offsets
        if (lane == 0) {
            stot = tot;
            atomicExch(&g_aggr[bid], tot | AGG_FLAG);
        }
    }
    // 4. spin on predecessors' aggregates (all 256 blocks co-resident:
    //    45.3 KB smem x 2 blocks/SM x 148 SMs = 296 >= 256)
    if (t < bid) {
        int v;
        do { v = *(volatile int*)&g_aggr[t]; } while (!(v & AGG_FLAG));
        sh[t] = v & 0xFFFF;
    }
    if (t == 0) sbase = 0;
    __syncthreads();
    {   // reduce sh[0..bid) into sbase
        int part = (t < bid) ? sh[t] : 0;
        #pragma unroll
        for (int o = 16; o; o >>= 1) part += __shfl_down_sync(0xffffffffu, part, o);
        if (lane == 0 && part) atomicAdd(&sbase, part);
    }
    __syncthreads();
    const int base = sbase, tot = stot;

    // 5. compact into SMEM staging
    if (occ) {
        int rl = swx[warp] + __popc(m & ((1u << lane) - 1u));   // local rank
        float inv = 1.0f / fmaxf(rb.w, 1.0f);
        float* om = &slab[7 * rl];
        om[0] = ra.x * inv; om[1] = ra.y * inv; om[2] = ra.z * inv; om[3] = ra.w * inv;
        om[4] = rb.x * inv; om[5] = rb.y * inv; om[6] = rb.z * inv;
        int idx = bid * HS_BLOCK + t;
        sco[3 * rl]     = (float)(idx >> 12);
        sco[3 * rl + 1] = (float)((idx >> 6) & 63);
        sco[3 * rl + 2] = (float)(idx & 63);
    }
    __syncthreads();

    // 6. coalesced streams out
    float* om = out + 7LL * base;
    for (int k = t; k < 7 * tot; k += HS_BLOCK) om[k] = slab[k];
    float* ou = out + 7LL * N + 3LL * base;
    for (int k = t; k < 3 * tot; k += HS_BLOCK) ou[k] = sco[k];

    // 7. block 255 knows n_unique = base + tot: record it and fill the
    //    sliver up to NM (expected empty; pathological cases stay correct).
    if (bid == HS_NBLOCKS - 1) {
        long long nu = (long long)base + tot;
        if (t == 0) g_nuniq = (int)nu;
        long long n7 = 7LL * N;
        fill_span(out, 7LL * nu,      7LL * NM,      0.f, t, HS_BLOCK);
        fill_span(out, n7 + 3LL * nu, n7 + 3LL * NM, -1.f, t, HS_BLOCK);
    }
}

extern "C" void kernel_launch(void* const* d_in, const int* in_sizes, int n_in,
                              void* d_out, int out_size) {
    const float* pts  = (const float*)d_in[0];
    const void*  grid = d_in[1];
    const int    N    = in_sizes[0] / 7;
    float*       out  = (float*)d_out;
    const long long NM = (N < NVOX) ? N : NVOX;   // upper bound on n_unique

    // 1. fused accumulate + guaranteed-tail fill (also zeroes g_aggr,
    //    detects dtype per block), Bresenham-interleaved roles
    int A = (N + 255) / 256;
    int F = A / 3; if (F < 1) F = 1;
    k_acc_fill<<<A + F, 256>>>(pts, grid, N, A, F, out, NM);

    // 2. single-pass scan + head rows + sliver + sums re-zero
    k_headscan<<<HS_NBLOCKS, HS_BLOCK>>>(out, N, NM);
}